// round 6
// baseline (speedup 1.0000x reference)
#include <cuda_runtime.h>

#define NN 50000
#define NE 400000
#define ND 128
#define ED 192
#define HD 256

typedef unsigned long long u64;

// Scratch: allocations are banned -> device globals.
__device__ __align__(16) float g_agg[(size_t)NN * HD];   // 51.2 MB
__device__ int g_src[NE];
__device__ int g_dst[NE];
__device__ unsigned g_flag;   // 0 => edge_index payload is int64

// ---- packed f32x2 helpers (FFMA2: 2x fp32 throughput vs 3-reg FFMA) -------
__device__ __forceinline__ u64 ffma2(u64 a, u64 b, u64 c) {
    u64 d; asm("fma.rn.f32x2 %0, %1, %2, %3;" : "=l"(d) : "l"(a), "l"(b), "l"(c)); return d;
}
__device__ __forceinline__ u64 dup2(float x) {
    u64 d; asm("mov.b64 %0, {%1, %1};" : "=l"(d) : "f"(x)); return d;
}
__device__ __forceinline__ void unpack2(u64 v, float& lo, float& hi) {
    asm("mov.b64 {%0, %1}, %2;" : "=f"(lo), "=f"(hi) : "l"(v));
}
__device__ __forceinline__ void cp16(float* s, const float* g) {
    unsigned sa = (unsigned)__cvta_generic_to_shared(s);
    asm volatile("cp.async.cg.shared.global [%0], [%1], 16;" :: "r"(sa), "l"(g));
}
__device__ __forceinline__ void cp_commit() { asm volatile("cp.async.commit_group;"); }
template<int W> __device__ __forceinline__ void cp_wait() {
    asm volatile("cp.async.wait_group %0;" :: "n"(W));
}

// mish(x) = x*tanh(softplus(x)) = x*(u^2+2u)/(u^2+2u+2), u = e^x
__device__ __forceinline__ float mish(float v) {
    if (v > 15.f) return v;
    float u = __expf(v);
    float w = u * (u + 2.f);
    return __fdividef(v * w, w + 2.f);
}

// ---------------- prologue kernels ------------------------------------------
__global__ void zero_agg_kernel() {
    size_t i = (size_t)blockIdx.x * blockDim.x + threadIdx.x;   // exact cover
    ((float4*)g_agg)[i] = make_float4(0.f, 0.f, 0.f, 0.f);
    if (i == 0) g_flag = 0u;
}

__global__ void detect_kernel(const unsigned* __restrict__ w) {
    unsigned loc = 0;
    for (int i = blockIdx.x * blockDim.x + threadIdx.x; i < NE;
         i += gridDim.x * blockDim.x)
        loc |= w[2 * i + 1];
    if (__syncthreads_or(loc != 0))
        if (threadIdx.x == 0) atomicOr(&g_flag, 1u);
}

__global__ void convert_kernel(const void* __restrict__ ei) {
    int i = blockIdx.x * blockDim.x + threadIdx.x;
    if (i >= NE) return;
    if (g_flag == 0u) {                              // int64 payload
        const long long* p = (const long long*)ei;
        g_src[i] = (int)p[i];
        g_dst[i] = (int)p[NE + i];
    } else {                                         // int32 payload
        const int* p = (const int*)ei;
        g_src[i] = p[i];
        g_dst[i] = p[NE + i];
    }
}

// ---------------- fused edge-message kernel ---------------------------------
// 64 edges/CTA, 256 threads. Thread tile: 8 edges x 8 cols (4 f32x2 pairs).
// smem: As[448][64] gather tile (later reused as H[64][256]) +
//       double-buffered 32x256 weight tiles via cp.async.
#define EDGE_SMEM ((448 * 64 + 2 * 32 * 256) * 4)

__global__ void __launch_bounds__(256, 1)
edge_kernel(const float* __restrict__ x, const float* __restrict__ ea,
            const float* __restrict__ W1, const float* __restrict__ b1,
            const float* __restrict__ W2, const float* __restrict__ b2)
{
    extern __shared__ float sm[];
    float* As = sm;               // 448*64
    float* Bs = sm + 448 * 64;    // 2 * 32*256
    __shared__ int sdst[64];

    const int tid = threadIdx.x;
    const int cx = tid & 31;      // cols [8cx, 8cx+8)
    const int cy = tid >> 5;      // rows [8cy, 8cy+8)

    // prefetch W1 stage 0 while gathering
    #pragma unroll
    for (int i = 0; i < 8; ++i) { int j = tid + 256 * i; cp16(Bs + j * 4, W1 + j * 4); }
    cp_commit();

    // gather m_in = [x[dst] | x[src] | edge_attr] transposed into As[k][e]
    {
        const int e = tid & 63;
        const int part = tid >> 6;                  // 4 threads per edge
        const int eg = blockIdx.x * 64 + e;
        const int sidx = g_src[eg];
        const int didx = g_dst[eg];
        if (part == 0) sdst[e] = didx;
        const float* xd = x + (size_t)didx * ND;
        const float* xs = x + (size_t)sidx * ND;
        const float* eap = ea + (size_t)eg * ED;
        #pragma unroll
        for (int c = 0; c < 28; ++c) {
            int k = (part * 28 + c) * 4;
            float4 v;
            if (k < 128)      v = *(const float4*)(xd + k);
            else if (k < 256) v = *(const float4*)(xs + (k - 128));
            else              v = *(const float4*)(eap + (k - 256));
            As[(k + 0) * 64 + e] = v.x;
            As[(k + 1) * 64 + e] = v.y;
            As[(k + 2) * 64 + e] = v.z;
            As[(k + 3) * 64 + e] = v.w;
        }
    }

    u64 acc[8][4];
    {
        const u64* bp = (const u64*)b1 + cx * 4;
        #pragma unroll
        for (int j = 0; j < 4; ++j) {
            u64 bv = bp[j];
            #pragma unroll
            for (int i = 0; i < 8; ++i) acc[i][j] = bv;
        }
    }

    // GEMM1: [64 x 448] @ [448 x 256]
    #pragma unroll 1
    for (int s = 0; s < 14; ++s) {
        if (s + 1 < 14) {
            const float* g = W1 + (s + 1) * 32 * 256;
            float* buf = Bs + ((s + 1) & 1) * (32 * 256);
            #pragma unroll
            for (int i = 0; i < 8; ++i) { int j = tid + 256 * i; cp16(buf + j * 4, g + j * 4); }
            cp_commit();
            cp_wait<1>();
        } else {
            cp_wait<0>();
        }
        __syncthreads();
        const float* Bsb = Bs + (s & 1) * (32 * 256);
        #pragma unroll 4
        for (int kk = 0; kk < 32; ++kk) {
            const float* arow = As + (s * 32 + kk) * 64 + cy * 8;   // warp-uniform
            float4 aA = *(const float4*)arow;
            float4 aB = *(const float4*)(arow + 4);
            const ulonglong2* brow = (const ulonglong2*)(Bsb + kk * 256 + cx * 8);
            ulonglong2 B0 = brow[0], B1 = brow[1];
            float av[8] = {aA.x, aA.y, aA.z, aA.w, aB.x, aB.y, aB.z, aB.w};
            #pragma unroll
            for (int i = 0; i < 8; ++i) {
                u64 ad = dup2(av[i]);
                acc[i][0] = ffma2(B0.x, ad, acc[i][0]);
                acc[i][1] = ffma2(B0.y, ad, acc[i][1]);
                acc[i][2] = ffma2(B1.x, ad, acc[i][2]);
                acc[i][3] = ffma2(B1.y, ad, acc[i][3]);
            }
        }
        __syncthreads();
    }

    // prefetch W2 stage 0
    #pragma unroll
    for (int i = 0; i < 8; ++i) { int j = tid + 256 * i; cp16(Bs + j * 4, W2 + j * 4); }
    cp_commit();

    // mish + write hidden H[64][256] (reuses As region)
    float* Hs = sm;
    #pragma unroll
    for (int i = 0; i < 8; ++i) {
        float v[8];
        #pragma unroll
        for (int j = 0; j < 4; ++j) unpack2(acc[i][j], v[2 * j], v[2 * j + 1]);
        #pragma unroll
        for (int j = 0; j < 8; ++j) v[j] = mish(v[j]);
        float* hp = Hs + (cy * 8 + i) * 256 + cx * 8;
        *(float4*)hp       = make_float4(v[0], v[1], v[2], v[3]);
        *(float4*)(hp + 4) = make_float4(v[4], v[5], v[6], v[7]);
    }

    {
        const u64* bp = (const u64*)b2 + cx * 4;
        #pragma unroll
        for (int j = 0; j < 4; ++j) {
            u64 bv = bp[j];
            #pragma unroll
            for (int i = 0; i < 8; ++i) acc[i][j] = bv;
        }
    }

    // GEMM2: [64 x 256] @ [256 x 256]
    #pragma unroll 1
    for (int s = 0; s < 8; ++s) {
        if (s + 1 < 8) {
            const float* g = W2 + (s + 1) * 32 * 256;
            float* buf = Bs + ((s + 1) & 1) * (32 * 256);
            #pragma unroll
            for (int i = 0; i < 8; ++i) { int j = tid + 256 * i; cp16(buf + j * 4, g + j * 4); }
            cp_commit();
            cp_wait<1>();
        } else {
            cp_wait<0>();
        }
        __syncthreads();
        const float* Bsb = Bs + (s & 1) * (32 * 256);
        const float* hbase = Hs + (cy * 8) * 256;
        #pragma unroll 4
        for (int kk = 0; kk < 32; ++kk) {
            int k = s * 32 + kk;
            const ulonglong2* brow = (const ulonglong2*)(Bsb + kk * 256 + cx * 8);
            ulonglong2 B0 = brow[0], B1 = brow[1];
            #pragma unroll
            for (int i = 0; i < 8; ++i) {
                u64 ad = dup2(hbase[i * 256 + k]);     // warp-uniform
                acc[i][0] = ffma2(B0.x, ad, acc[i][0]);
                acc[i][1] = ffma2(B0.y, ad, acc[i][1]);
                acc[i][2] = ffma2(B1.x, ad, acc[i][2]);
                acc[i][3] = ffma2(B1.y, ad, acc[i][3]);
            }
        }
        __syncthreads();
    }

    // scatter-add msg into g_agg[dst] (atomicAdd w/ unused return -> REDG)
    #pragma unroll
    for (int i = 0; i < 8; ++i) {
        float v[8];
        #pragma unroll
        for (int j = 0; j < 4; ++j) unpack2(acc[i][j], v[2 * j], v[2 * j + 1]);
        float* p = g_agg + (size_t)sdst[cy * 8 + i] * HD + cx * 8;
        #pragma unroll
        for (int j = 0; j < 8; ++j) atomicAdd(p + j, v[j]);
    }
}

// ---------------- fused node-update kernel ----------------------------------
// 64 nodes/CTA, 256 threads. Layer1 tile 8x8 (out 256); layer2 tile 4x8
// (out 128); then residual + warp-shuffle LayerNorm.
#define NODE_SMEM ((384 * 64 + 2 * 32 * 256) * 4)

__global__ void __launch_bounds__(256, 1)
node_kernel(const float* __restrict__ x,
            const float* __restrict__ U1, const float* __restrict__ c1,
            const float* __restrict__ U2, const float* __restrict__ c2,
            const float* __restrict__ gamma, const float* __restrict__ beta,
            float* __restrict__ out)
{
    extern __shared__ float sm[];
    float* As = sm;               // 384*64
    float* Bs = sm + 384 * 64;    // 2 * 32*256
    const int tid = threadIdx.x;
    const int cx = tid & 31, cy = tid >> 5;
    const int nbase = blockIdx.x * 64;

    // prefetch U1 stage 0
    #pragma unroll
    for (int i = 0; i < 8; ++i) { int j = tid + 256 * i; cp16(Bs + j * 4, U1 + j * 4); }
    cp_commit();

    // gather [x | agg] transposed into As[k][n]
    {
        const int e = tid & 63;
        const int part = tid >> 6;
        int node = nbase + e;
        if (node >= NN) node = 0;
        const float* xp = x + (size_t)node * ND;
        const float* ap = g_agg + (size_t)node * HD;
        #pragma unroll
        for (int c = 0; c < 24; ++c) {
            int k = (part * 24 + c) * 4;
            float4 v = (k < 128) ? *(const float4*)(xp + k)
                                 : *(const float4*)(ap + (k - 128));
            As[(k + 0) * 64 + e] = v.x;
            As[(k + 1) * 64 + e] = v.y;
            As[(k + 2) * 64 + e] = v.z;
            As[(k + 3) * 64 + e] = v.w;
        }
    }

    u64 acc[8][4];
    {
        const u64* bp = (const u64*)c1 + cx * 4;
        #pragma unroll
        for (int j = 0; j < 4; ++j) {
            u64 bv = bp[j];
            #pragma unroll
            for (int i = 0; i < 8; ++i) acc[i][j] = bv;
        }
    }

    // GEMM1: [64 x 384] @ [384 x 256]
    #pragma unroll 1
    for (int s = 0; s < 12; ++s) {
        if (s + 1 < 12) {
            const float* g = U1 + (s + 1) * 32 * 256;
            float* buf = Bs + ((s + 1) & 1) * (32 * 256);
            #pragma unroll
            for (int i = 0; i < 8; ++i) { int j = tid + 256 * i; cp16(buf + j * 4, g + j * 4); }
            cp_commit();
            cp_wait<1>();
        } else {
            cp_wait<0>();
        }
        __syncthreads();
        const float* Bsb = Bs + (s & 1) * (32 * 256);
        #pragma unroll 4
        for (int kk = 0; kk < 32; ++kk) {
            const float* arow = As + (s * 32 + kk) * 64 + cy * 8;
            float4 aA = *(const float4*)arow;
            float4 aB = *(const float4*)(arow + 4);
            const ulonglong2* brow = (const ulonglong2*)(Bsb + kk * 256 + cx * 8);
            ulonglong2 B0 = brow[0], B1 = brow[1];
            float av[8] = {aA.x, aA.y, aA.z, aA.w, aB.x, aB.y, aB.z, aB.w};
            #pragma unroll
            for (int i = 0; i < 8; ++i) {
                u64 ad = dup2(av[i]);
                acc[i][0] = ffma2(B0.x, ad, acc[i][0]);
                acc[i][1] = ffma2(B0.y, ad, acc[i][1]);
                acc[i][2] = ffma2(B1.x, ad, acc[i][2]);
                acc[i][3] = ffma2(B1.y, ad, acc[i][3]);
            }
        }
        __syncthreads();
    }

    // prefetch U2 stage 0 (32x128 floats = 1024 float4, 4 per thread)
    #pragma unroll
    for (int i = 0; i < 4; ++i) { int j = tid + 256 * i; cp16(Bs + j * 4, U2 + j * 4); }
    cp_commit();

    // mish -> H[64][256] (reuses As region)
    float* Hs = sm;
    #pragma unroll
    for (int i = 0; i < 8; ++i) {
        float v[8];
        #pragma unroll
        for (int j = 0; j < 4; ++j) unpack2(acc[i][j], v[2 * j], v[2 * j + 1]);
        #pragma unroll
        for (int j = 0; j < 8; ++j) v[j] = mish(v[j]);
        float* hp = Hs + (cy * 8 + i) * 256 + cx * 8;
        *(float4*)hp       = make_float4(v[0], v[1], v[2], v[3]);
        *(float4*)(hp + 4) = make_float4(v[4], v[5], v[6], v[7]);
    }

    // GEMM2: [64 x 256] @ [256 x 128], tile 4 rows x 8 cols per thread
    const int cx2 = tid & 15, cy2 = tid >> 4;
    u64 acc2[4][4];
    {
        const u64* bp = (const u64*)c2 + cx2 * 4;
        #pragma unroll
        for (int j = 0; j < 4; ++j) {
            u64 bv = bp[j];
            #pragma unroll
            for (int i = 0; i < 4; ++i) acc2[i][j] = bv;
        }
    }

    #pragma unroll 1
    for (int s = 0; s < 8; ++s) {
        if (s + 1 < 8) {
            const float* g = U2 + (s + 1) * 32 * 128;
            float* buf = Bs + ((s + 1) & 1) * (32 * 256);
            #pragma unroll
            for (int i = 0; i < 4; ++i) { int j = tid + 256 * i; cp16(buf + j * 4, g + j * 4); }
            cp_commit();
            cp_wait<1>();
        } else {
            cp_wait<0>();
        }
        __syncthreads();
        const float* Bsb = Bs + (s & 1) * (32 * 256);
        const float* hbase = Hs + (cy2 * 4) * 256;
        #pragma unroll 4
        for (int kk = 0; kk < 32; ++kk) {
            int k = s * 32 + kk;
            const ulonglong2* brow = (const ulonglong2*)(Bsb + kk * 128 + cx2 * 8);
            ulonglong2 B0 = brow[0], B1 = brow[1];
            #pragma unroll
            for (int i = 0; i < 4; ++i) {
                u64 ad = dup2(hbase[i * 256 + k]);
                acc2[i][0] = ffma2(B0.x, ad, acc2[i][0]);
                acc2[i][1] = ffma2(B0.y, ad, acc2[i][1]);
                acc2[i][2] = ffma2(B1.x, ad, acc2[i][2]);
                acc2[i][3] = ffma2(B1.y, ad, acc2[i][3]);
            }
        }
        __syncthreads();
    }

    // y = x + upd -> Ys[64][128] (reuses Bs region; last GEMM reads synced)
    float* Ys = Bs;
    #pragma unroll
    for (int i = 0; i < 4; ++i) {
        int row = cy2 * 4 + i;
        int node = nbase + row;
        float v[8];
        #pragma unroll
        for (int j = 0; j < 4; ++j) unpack2(acc2[i][j], v[2 * j], v[2 * j + 1]);
        if (node < NN) {
            const float* xp = x + (size_t)node * ND + cx2 * 8;
            #pragma unroll
            for (int j = 0; j < 8; ++j) v[j] += xp[j];
        }
        float* yp = Ys + row * 128 + cx2 * 8;
        *(float4*)yp       = make_float4(v[0], v[1], v[2], v[3]);
        *(float4*)(yp + 4) = make_float4(v[4], v[5], v[6], v[7]);
    }
    __syncthreads();

    // LayerNorm: 4 threads per row, each owns 32 cols
    {
        const int row = tid >> 2, q = tid & 3;
        const float* yr = Ys + row * 128 + q * 32;
        float vv[32];
        float s1 = 0.f, s2 = 0.f;
        #pragma unroll
        for (int j = 0; j < 32; j += 4) {
            float4 t = *(const float4*)(yr + j);
            vv[j] = t.x; vv[j + 1] = t.y; vv[j + 2] = t.z; vv[j + 3] = t.w;
            s1 += t.x + t.y + t.z + t.w;
            s2 += t.x * t.x + t.y * t.y + t.z * t.z + t.w * t.w;
        }
        s1 += __shfl_xor_sync(0xFFFFFFFFu, s1, 1);
        s2 += __shfl_xor_sync(0xFFFFFFFFu, s2, 1);
        s1 += __shfl_xor_sync(0xFFFFFFFFu, s1, 2);
        s2 += __shfl_xor_sync(0xFFFFFFFFu, s2, 2);
        float mu = s1 * (1.f / 128.f);
        float var = s2 * (1.f / 128.f) - mu * mu;
        float r = rsqrtf(var + 1e-5f);
        int node = nbase + row;
        if (node < NN) {
            float* op = out + (size_t)node * ND + q * 32;
            const float* gp = gamma + q * 32;
            const float* bp = beta + q * 32;
            #pragma unroll
            for (int j = 0; j < 32; j += 4) {
                float4 g4 = *(const float4*)(gp + j);
                float4 b4 = *(const float4*)(bp + j);
                float4 o;
                o.x = (vv[j]     - mu) * r * g4.x + b4.x;
                o.y = (vv[j + 1] - mu) * r * g4.y + b4.y;
                o.z = (vv[j + 2] - mu) * r * g4.z + b4.z;
                o.w = (vv[j + 3] - mu) * r * g4.w + b4.w;
                *(float4*)(op + j) = o;
            }
        }
    }
}

// ---------------- launch ------------------------------------------------
extern "C" void kernel_launch(void* const* d_in, const int* in_sizes, int n_in,
                              void* d_out, int out_size) {
    (void)in_sizes; (void)n_in; (void)out_size;
    const float* x     = (const float*)d_in[0];
    const void*  ei    = d_in[1];
    const float* ea    = (const float*)d_in[2];
    const float* W1    = (const float*)d_in[3];
    const float* b1    = (const float*)d_in[4];
    const float* W2    = (const float*)d_in[5];
    const float* b2    = (const float*)d_in[6];
    const float* U1    = (const float*)d_in[7];
    const float* c1    = (const float*)d_in[8];
    const float* U2    = (const float*)d_in[9];
    const float* c2    = (const float*)d_in[10];
    const float* gamma = (const float*)d_in[11];
    const float* beta  = (const float*)d_in[12];
    float* out = (float*)d_out;

    static bool attr_set = false;
    if (!attr_set) {
        cudaFuncSetAttribute(edge_kernel, cudaFuncAttributeMaxDynamicSharedMemorySize, EDGE_SMEM);
        cudaFuncSetAttribute(node_kernel, cudaFuncAttributeMaxDynamicSharedMemorySize, NODE_SMEM);
        attr_set = true;
    }

    zero_agg_kernel<<<12500, 256>>>();
    detect_kernel<<<128, 256>>>((const unsigned*)ei);
    convert_kernel<<<(NE + 255) / 256, 256>>>(ei);
    edge_kernel<<<NE / 64, 256, EDGE_SMEM>>>(x, ea, W1, b1, W2, b2);
    node_kernel<<<(NN + 63) / 64, 256, NODE_SMEM>>>(x, U1, c1, U2, c2, gamma, beta, out);
}

// round 8
// speedup vs baseline: 1.2697x; 1.2697x over previous
#include <cuda_runtime.h>

#define NN 50000
#define NE 400000
#define ND 128
#define ED 192
#define HD 256

typedef unsigned long long u64;

// Scratch: allocations banned -> device globals.
__device__ __align__(16) float g_agg[(size_t)NN * HD];   // 51.2 MB
__device__ int g_src[NE];
__device__ int g_dst[NE];
__device__ unsigned g_flag;   // 0 => edge_index payload is int64

// ---- packed f32x2 helpers (FFMA2: 2x fp32 throughput) ----------------------
__device__ __forceinline__ u64 ffma2(u64 a, u64 b, u64 c) {
    u64 d; asm("fma.rn.f32x2 %0, %1, %2, %3;" : "=l"(d) : "l"(a), "l"(b), "l"(c)); return d;
}
__device__ __forceinline__ u64 dup2(float x) {
    u64 d; asm("mov.b64 %0, {%1, %1};" : "=l"(d) : "f"(x)); return d;
}
__device__ __forceinline__ void unpack2(u64 v, float& lo, float& hi) {
    asm("mov.b64 {%0, %1}, %2;" : "=f"(lo), "=f"(hi) : "l"(v));
}
__device__ __forceinline__ void cp16(float* s, const float* g) {
    unsigned sa = (unsigned)__cvta_generic_to_shared(s);
    asm volatile("cp.async.cg.shared.global [%0], [%1], 16;" :: "r"(sa), "l"(g));
}
__device__ __forceinline__ void cp_commit() { asm volatile("cp.async.commit_group;"); }
template<int W> __device__ __forceinline__ void cp_wait() {
    asm volatile("cp.async.wait_group %0;" :: "n"(W));
}
// vector reduction to gmem (no return): 4x less LSU issue than scalar atomics
__device__ __forceinline__ void red4(float* p, float a, float b, float c, float d) {
    asm volatile("red.global.add.v4.f32 [%0], {%1,%2,%3,%4};"
                 :: "l"(p), "f"(a), "f"(b), "f"(c), "f"(d) : "memory");
}

// mish(x) = x*tanh(softplus(x)) = x*(u^2+2u)/(u^2+2u+2), u = e^x
__device__ __forceinline__ float mish(float v) {
    if (v > 15.f) return v;
    float u = __expf(v);
    float w = u * (u + 2.f);
    return __fdividef(v * w, w + 2.f);
}

// ---------------- prologue kernels ------------------------------------------
__global__ void zero_agg_kernel() {
    size_t i = (size_t)blockIdx.x * blockDim.x + threadIdx.x;   // exact cover
    ((float4*)g_agg)[i] = make_float4(0.f, 0.f, 0.f, 0.f);
    if (i == 0) g_flag = 0u;
}

__global__ void detect_kernel(const unsigned* __restrict__ w) {
    unsigned loc = 0;
    for (int i = blockIdx.x * blockDim.x + threadIdx.x; i < NE;
         i += gridDim.x * blockDim.x)
        loc |= w[2 * i + 1];
    if (__syncthreads_or(loc != 0))
        if (threadIdx.x == 0) atomicOr(&g_flag, 1u);
}

__global__ void convert_kernel(const void* __restrict__ ei) {
    int i = blockIdx.x * blockDim.x + threadIdx.x;
    if (i >= NE) return;
    if (g_flag == 0u) {                              // int64 payload
        const long long* p = (const long long*)ei;
        g_src[i] = (int)p[i];
        g_dst[i] = (int)p[NE + i];
    } else {                                         // int32 payload
        const int* p = (const int*)ei;
        g_src[i] = p[i];
        g_dst[i] = p[NE + i];
    }
}

// ---------------- fused edge-message kernel ---------------------------------
// 64 edges/CTA, 256 threads, thread tile 8x8 (f32x2 accs).
// smem (floats): [0,4096)       A dbuf (2 x 32k x 64) / GEMM2 W2 buf1
//                [4096,20480)   B dbuf (2 x 32k x 256) / H[64][256]
//                [20480,24576)  W2 buf0 (16k x 256)
// Total 96 KB -> 2 CTAs/SM.
#define EB_OFF 4096
#define EW_OFF 20480
#define EDGE_SMEM (24576 * 4)

__global__ void __launch_bounds__(256, 2)
edge_kernel(const float* __restrict__ x, const float* __restrict__ ea,
            const float* __restrict__ W1, const float* __restrict__ b1,
            const float* __restrict__ W2, const float* __restrict__ b2)
{
    extern __shared__ float sm[];
    __shared__ int sdst[64];

    const int tid = threadIdx.x;
    const int cx = tid & 31;      // cols [8cx, 8cx+8)
    const int cy = tid >> 5;      // rows [8cy, 8cy+8)
    const int e = tid & 63;       // gather: edge within CTA
    const int part = tid >> 6;    // gather: 4 threads per edge, 8 k each

    const int eg = blockIdx.x * 64 + e;
    const int sidx = g_src[eg], didx = g_dst[eg];
    if (part == 0) sdst[e] = didx;
    const float* xd  = x + (size_t)didx * ND;
    const float* xs  = x + (size_t)sidx * ND;
    const float* eap = ea + (size_t)eg * ED;

    // prologue: gather chunk 0, prefetch W1 chunk 0
    {
        int kb = part * 8;
        const float* p = xd + kb;   // chunk 0 always in x[dst]
        float4 r0 = *(const float4*)p, r1 = *(const float4*)(p + 4);
        float* a = sm + (part * 8) * 64 + e;
        a[0] = r0.x; a[64] = r0.y; a[128] = r0.z; a[192] = r0.w;
        a[256] = r1.x; a[320] = r1.y; a[384] = r1.z; a[448] = r1.w;
    }
    #pragma unroll
    for (int i = 0; i < 8; ++i) { int j = tid + 256 * i; cp16(sm + EB_OFF + j * 4, W1 + j * 4); }
    cp_commit();

    u64 acc[8][4];
    {
        const u64* bp = (const u64*)b1 + cx * 4;
        #pragma unroll
        for (int j = 0; j < 4; ++j) {
            u64 bv = bp[j];
            #pragma unroll
            for (int i = 0; i < 8; ++i) acc[i][j] = bv;
        }
    }

    // GEMM1: [64 x 448] @ [448 x 256], 14 k-chunks of 32
    #pragma unroll 1
    for (int s = 0; s < 14; ++s) {
        cp_wait<0>();
        __syncthreads();
        float4 r0, r1;
        const bool more = (s + 1 < 14);
        if (more) {
            const float* g = W1 + (s + 1) * 8192;
            float* buf = sm + EB_OFF + ((s + 1) & 1) * 8192;
            #pragma unroll
            for (int i = 0; i < 8; ++i) { int j = tid + 256 * i; cp16(buf + j * 4, g + j * 4); }
            cp_commit();
            int kb = 32 * (s + 1) + part * 8;
            const float* p = (kb < 128) ? xd + kb
                           : (kb < 256) ? xs + (kb - 128)
                                        : eap + (kb - 256);
            r0 = *(const float4*)p; r1 = *(const float4*)(p + 4);
        } else {
            // prefetch W2 chunk 0 into the idle EW region
            #pragma unroll
            for (int i = 0; i < 4; ++i) { int j = tid + 256 * i; cp16(sm + EW_OFF + j * 4, W2 + j * 4); }
            cp_commit();
        }
        const float* Asb = sm + (s & 1) * 2048;
        const float* Bsb = sm + EB_OFF + (s & 1) * 8192;
        #pragma unroll 4
        for (int kk = 0; kk < 32; ++kk) {
            const float* arow = Asb + kk * 64 + cy * 8;   // warp-uniform bcast
            float4 aA = *(const float4*)arow;
            float4 aB = *(const float4*)(arow + 4);
            const ulonglong2* brow = (const ulonglong2*)(Bsb + kk * 256 + cx * 8);
            ulonglong2 B0 = brow[0], B1 = brow[1];
            float av[8] = {aA.x, aA.y, aA.z, aA.w, aB.x, aB.y, aB.z, aB.w};
            #pragma unroll
            for (int i = 0; i < 8; ++i) {
                u64 ad = dup2(av[i]);
                acc[i][0] = ffma2(B0.x, ad, acc[i][0]);
                acc[i][1] = ffma2(B0.y, ad, acc[i][1]);
                acc[i][2] = ffma2(B1.x, ad, acc[i][2]);
                acc[i][3] = ffma2(B1.y, ad, acc[i][3]);
            }
        }
        if (more) {
            float* a = sm + ((s + 1) & 1) * 2048 + (part * 8) * 64 + e;
            a[0] = r0.x; a[64] = r0.y; a[128] = r0.z; a[192] = r0.w;
            a[256] = r1.x; a[320] = r1.y; a[384] = r1.z; a[448] = r1.w;
        }
    }

    __syncthreads();   // all GEMM1 smem reads done before H overwrites B region

    // mish -> H[64][256] in the B region
    float* Hs = sm + EB_OFF;
    #pragma unroll
    for (int i = 0; i < 8; ++i) {
        float v[8];
        #pragma unroll
        for (int j = 0; j < 4; ++j) unpack2(acc[i][j], v[2 * j], v[2 * j + 1]);
        #pragma unroll
        for (int j = 0; j < 8; ++j) v[j] = mish(v[j]);
        float* hp = Hs + (cy * 8 + i) * 256 + cx * 8;
        *(float4*)hp       = make_float4(v[0], v[1], v[2], v[3]);
        *(float4*)(hp + 4) = make_float4(v[4], v[5], v[6], v[7]);
    }

    {
        const u64* bp = (const u64*)b2 + cx * 4;
        #pragma unroll
        for (int j = 0; j < 4; ++j) {
            u64 bv = bp[j];
            #pragma unroll
            for (int i = 0; i < 8; ++i) acc[i][j] = bv;
        }
    }

    // GEMM2: [64 x 256] @ [256 x 256], 16 k-chunks of 16, W2 dbuf EW/A regions
    #pragma unroll 1
    for (int s = 0; s < 16; ++s) {
        cp_wait<0>();
        __syncthreads();
        if (s + 1 < 16) {
            const float* g = W2 + (s + 1) * 4096;
            float* buf = ((s + 1) & 1) ? sm : sm + EW_OFF;
            #pragma unroll
            for (int i = 0; i < 4; ++i) { int j = tid + 256 * i; cp16(buf + j * 4, g + j * 4); }
            cp_commit();
        }
        const float* Bsb = (s & 1) ? sm : sm + EW_OFF;
        const float* hbase = Hs + (cy * 8) * 256;
        #pragma unroll 4
        for (int kk = 0; kk < 16; ++kk) {
            int k = s * 16 + kk;
            const ulonglong2* brow = (const ulonglong2*)(Bsb + kk * 256 + cx * 8);
            ulonglong2 B0 = brow[0], B1 = brow[1];
            #pragma unroll
            for (int i = 0; i < 8; ++i) {
                u64 ad = dup2(hbase[i * 256 + k]);   // warp-uniform bcast
                acc[i][0] = ffma2(B0.x, ad, acc[i][0]);
                acc[i][1] = ffma2(B0.y, ad, acc[i][1]);
                acc[i][2] = ffma2(B1.x, ad, acc[i][2]);
                acc[i][3] = ffma2(B1.y, ad, acc[i][3]);
            }
        }
    }

    // scatter-add msg into g_agg[dst] via vector REDG
    #pragma unroll
    for (int i = 0; i < 8; ++i) {
        float v[8];
        #pragma unroll
        for (int j = 0; j < 4; ++j) unpack2(acc[i][j], v[2 * j], v[2 * j + 1]);
        float* p = g_agg + (size_t)sdst[cy * 8 + i] * HD + cx * 8;
        red4(p,     v[0], v[1], v[2], v[3]);
        red4(p + 4, v[4], v[5], v[6], v[7]);
    }
}

// ---------------- fused node-update kernel ----------------------------------
// 64 nodes/CTA, 256 threads. GEMM1 tile 8x8 (out 256); GEMM2 tile 4x8
// (out 128); residual + register LayerNorm (shfl over 16-lane groups).
// smem (floats): [0,4096) A dbuf / U2 buf1; [4096,20480) U1 dbuf / H;
//                [20480,24576) U2 buf0. Total 96 KB -> 2 CTAs/SM.
#define NODE_SMEM (24576 * 4)

__global__ void __launch_bounds__(256, 2)
node_kernel(const float* __restrict__ x,
            const float* __restrict__ U1, const float* __restrict__ c1,
            const float* __restrict__ U2, const float* __restrict__ c2,
            const float* __restrict__ gamma, const float* __restrict__ beta,
            float* __restrict__ out)
{
    extern __shared__ float sm[];
    const int tid = threadIdx.x;
    const int cx = tid & 31, cy = tid >> 5;
    const int e = tid & 63, part = tid >> 6;
    const int nbase = blockIdx.x * 64;

    int gnode = nbase + e;
    if (gnode >= NN) gnode = 0;
    const float* xp = x + (size_t)gnode * ND;
    const float* ap = g_agg + (size_t)gnode * HD;

    // prologue: gather chunk 0, prefetch U1 chunk 0
    {
        int kb = part * 8;
        const float* p = xp + kb;   // chunk 0 in x
        float4 r0 = *(const float4*)p, r1 = *(const float4*)(p + 4);
        float* a = sm + (part * 8) * 64 + e;
        a[0] = r0.x; a[64] = r0.y; a[128] = r0.z; a[192] = r0.w;
        a[256] = r1.x; a[320] = r1.y; a[384] = r1.z; a[448] = r1.w;
    }
    #pragma unroll
    for (int i = 0; i < 8; ++i) { int j = tid + 256 * i; cp16(sm + EB_OFF + j * 4, U1 + j * 4); }
    cp_commit();

    u64 acc[8][4];
    {
        const u64* bp = (const u64*)c1 + cx * 4;
        #pragma unroll
        for (int j = 0; j < 4; ++j) {
            u64 bv = bp[j];
            #pragma unroll
            for (int i = 0; i < 8; ++i) acc[i][j] = bv;
        }
    }

    // GEMM1: [64 x 384] @ [384 x 256], 12 k-chunks of 32
    #pragma unroll 1
    for (int s = 0; s < 12; ++s) {
        cp_wait<0>();
        __syncthreads();
        float4 r0, r1;
        const bool more = (s + 1 < 12);
        if (more) {
            const float* g = U1 + (s + 1) * 8192;
            float* buf = sm + EB_OFF + ((s + 1) & 1) * 8192;
            #pragma unroll
            for (int i = 0; i < 8; ++i) { int j = tid + 256 * i; cp16(buf + j * 4, g + j * 4); }
            cp_commit();
            int kb = 32 * (s + 1) + part * 8;
            const float* p = (kb < 128) ? xp + kb : ap + (kb - 128);
            r0 = *(const float4*)p; r1 = *(const float4*)(p + 4);
        } else {
            // prefetch U2 chunk 0
            #pragma unroll
            for (int i = 0; i < 4; ++i) { int j = tid + 256 * i; cp16(sm + EW_OFF + j * 4, U2 + j * 4); }
            cp_commit();
        }
        const float* Asb = sm + (s & 1) * 2048;
        const float* Bsb = sm + EB_OFF + (s & 1) * 8192;
        #pragma unroll 4
        for (int kk = 0; kk < 32; ++kk) {
            const float* arow = Asb + kk * 64 + cy * 8;
            float4 aA = *(const float4*)arow;
            float4 aB = *(const float4*)(arow + 4);
            const ulonglong2* brow = (const ulonglong2*)(Bsb + kk * 256 + cx * 8);
            ulonglong2 B0 = brow[0], B1 = brow[1];
            float av[8] = {aA.x, aA.y, aA.z, aA.w, aB.x, aB.y, aB.z, aB.w};
            #pragma unroll
            for (int i = 0; i < 8; ++i) {
                u64 ad = dup2(av[i]);
                acc[i][0] = ffma2(B0.x, ad, acc[i][0]);
                acc[i][1] = ffma2(B0.y, ad, acc[i][1]);
                acc[i][2] = ffma2(B1.x, ad, acc[i][2]);
                acc[i][3] = ffma2(B1.y, ad, acc[i][3]);
            }
        }
        if (more) {
            float* a = sm + ((s + 1) & 1) * 2048 + (part * 8) * 64 + e;
            a[0] = r0.x; a[64] = r0.y; a[128] = r0.z; a[192] = r0.w;
            a[256] = r1.x; a[320] = r1.y; a[384] = r1.z; a[448] = r1.w;
        }
    }

    __syncthreads();

    // mish -> H[64][256]
    float* Hs = sm + EB_OFF;
    #pragma unroll
    for (int i = 0; i < 8; ++i) {
        float v[8];
        #pragma unroll
        for (int j = 0; j < 4; ++j) unpack2(acc[i][j], v[2 * j], v[2 * j + 1]);
        #pragma unroll
        for (int j = 0; j < 8; ++j) v[j] = mish(v[j]);
        float* hp = Hs + (cy * 8 + i) * 256 + cx * 8;
        *(float4*)hp       = make_float4(v[0], v[1], v[2], v[3]);
        *(float4*)(hp + 4) = make_float4(v[4], v[5], v[6], v[7]);
    }

    // GEMM2: [64 x 256] @ [256 x 128], 8 k-chunks of 32, tile 4x8
    const int cx2 = tid & 15, cy2 = tid >> 4;
    u64 acc2[4][4];
    {
        const u64* bp = (const u64*)c2 + cx2 * 4;
        #pragma unroll
        for (int j = 0; j < 4; ++j) {
            u64 bv = bp[j];
            #pragma unroll
            for (int i = 0; i < 4; ++i) acc2[i][j] = bv;
        }
    }

    #pragma unroll 1
    for (int s = 0; s < 8; ++s) {
        cp_wait<0>();
        __syncthreads();
        if (s + 1 < 8) {
            const float* g = U2 + (s + 1) * 4096;
            float* buf = ((s + 1) & 1) ? sm : sm + EW_OFF;
            #pragma unroll
            for (int i = 0; i < 4; ++i) { int j = tid + 256 * i; cp16(buf + j * 4, g + j * 4); }
            cp_commit();
        }
        const float* Bsb = (s & 1) ? sm : sm + EW_OFF;
        const float* hbase = Hs + (cy2 * 4) * 256;
        #pragma unroll 4
        for (int kk = 0; kk < 32; ++kk) {
            int k = s * 32 + kk;
            const ulonglong2* brow = (const ulonglong2*)(Bsb + kk * 128 + cx2 * 8);
            ulonglong2 B0 = brow[0], B1 = brow[1];
            #pragma unroll
            for (int i = 0; i < 4; ++i) {
                u64 ad = dup2(hbase[i * 256 + k]);
                acc2[i][0] = ffma2(B0.x, ad, acc2[i][0]);
                acc2[i][1] = ffma2(B0.y, ad, acc2[i][1]);
                acc2[i][2] = ffma2(B1.x, ad, acc2[i][2]);
                acc2[i][3] = ffma2(B1.y, ad, acc2[i][3]);
            }
        }
    }

    // residual + LayerNorm entirely in registers (16-lane shfl groups per row)
    float g8[8], be8[8];
    {
        float4 t0 = *(const float4*)(gamma + cx2 * 8);
        float4 t1 = *(const float4*)(gamma + cx2 * 8 + 4);
        g8[0]=t0.x; g8[1]=t0.y; g8[2]=t0.z; g8[3]=t0.w;
        g8[4]=t1.x; g8[5]=t1.y; g8[6]=t1.z; g8[7]=t1.w;
        float4 u0 = *(const float4*)(beta + cx2 * 8);
        float4 u1 = *(const float4*)(beta + cx2 * 8 + 4);
        be8[0]=u0.x; be8[1]=u0.y; be8[2]=u0.z; be8[3]=u0.w;
        be8[4]=u1.x; be8[5]=u1.y; be8[6]=u1.z; be8[7]=u1.w;
    }
    #pragma unroll
    for (int i = 0; i < 4; ++i) {
        const int row = cy2 * 4 + i;
        const int node = nbase + row;
        float v[8];
        #pragma unroll
        for (int j = 0; j < 4; ++j) unpack2(acc2[i][j], v[2 * j], v[2 * j + 1]);
        if (node < NN) {
            const float* xr = x + (size_t)node * ND + cx2 * 8;
            float4 r0 = *(const float4*)xr, r1 = *(const float4*)(xr + 4);
            v[0]+=r0.x; v[1]+=r0.y; v[2]+=r0.z; v[3]+=r0.w;
            v[4]+=r1.x; v[5]+=r1.y; v[6]+=r1.z; v[7]+=r1.w;
        }
        float s1 = 0.f, s2 = 0.f;
        #pragma unroll
        for (int j = 0; j < 8; ++j) { s1 += v[j]; s2 += v[j] * v[j]; }
        #pragma unroll
        for (int off = 1; off < 16; off <<= 1) {
            s1 += __shfl_xor_sync(0xFFFFFFFFu, s1, off);
            s2 += __shfl_xor_sync(0xFFFFFFFFu, s2, off);
        }
        float mu = s1 * (1.f / 128.f);
        float var = s2 * (1.f / 128.f) - mu * mu;
        float r = rsqrtf(var + 1e-5f);
        if (node < NN) {
            float* op = out + (size_t)node * ND + cx2 * 8;
            float4 o0, o1;
            o0.x = (v[0]-mu)*r*g8[0]+be8[0]; o0.y = (v[1]-mu)*r*g8[1]+be8[1];
            o0.z = (v[2]-mu)*r*g8[2]+be8[2]; o0.w = (v[3]-mu)*r*g8[3]+be8[3];
            o1.x = (v[4]-mu)*r*g8[4]+be8[4]; o1.y = (v[5]-mu)*r*g8[5]+be8[5];
            o1.z = (v[6]-mu)*r*g8[6]+be8[6]; o1.w = (v[7]-mu)*r*g8[7]+be8[7];
            *(float4*)op       = o0;
            *(float4*)(op + 4) = o1;
        }
    }
}

// ---------------- launch ------------------------------------------------
extern "C" void kernel_launch(void* const* d_in, const int* in_sizes, int n_in,
                              void* d_out, int out_size) {
    (void)in_sizes; (void)n_in; (void)out_size;
    const float* x     = (const float*)d_in[0];
    const void*  ei    = d_in[1];
    const float* ea    = (const float*)d_in[2];
    const float* W1    = (const float*)d_in[3];
    const float* b1    = (const float*)d_in[4];
    const float* W2    = (const float*)d_in[5];
    const float* b2    = (const float*)d_in[6];
    const float* U1    = (const float*)d_in[7];
    const float* c1    = (const float*)d_in[8];
    const float* U2    = (const float*)d_in[9];
    const float* c2    = (const float*)d_in[10];
    const float* gamma = (const float*)d_in[11];
    const float* beta  = (const float*)d_in[12];
    float* out = (float*)d_out;

    static bool attr_set = false;
    if (!attr_set) {
        cudaFuncSetAttribute(edge_kernel, cudaFuncAttributeMaxDynamicSharedMemorySize, EDGE_SMEM);
        cudaFuncSetAttribute(node_kernel, cudaFuncAttributeMaxDynamicSharedMemorySize, NODE_SMEM);
        attr_set = true;
    }

    zero_agg_kernel<<<12500, 256>>>();
    detect_kernel<<<128, 256>>>((const unsigned*)ei);
    convert_kernel<<<(NE + 255) / 256, 256>>>(ei);
    edge_kernel<<<NE / 64, 256, EDGE_SMEM>>>(x, ea, W1, b1, W2, b2);
    node_kernel<<<(NN + 63) / 64, 256, NODE_SMEM>>>(x, U1, c1, U2, c2, gamma, beta, out);
}

// round 9
// speedup vs baseline: 1.2702x; 1.0004x over previous
#include <cuda_runtime.h>

#define NN 50000
#define NE 400000
#define ND 128
#define ED 192
#define HD 256

typedef unsigned long long u64;

// Scratch: allocations banned -> device globals.
__device__ __align__(16) float g_agg[(size_t)NN * HD];   // 51.2 MB
__device__ int g_src[NE];
__device__ int g_dst[NE];
__device__ unsigned g_flag;   // 0 => edge_index payload is int64

// ---- packed f32x2 helpers (FFMA2: 2x fp32 throughput) ----------------------
__device__ __forceinline__ u64 ffma2(u64 a, u64 b, u64 c) {
    u64 d; asm("fma.rn.f32x2 %0, %1, %2, %3;" : "=l"(d) : "l"(a), "l"(b), "l"(c)); return d;
}
__device__ __forceinline__ u64 dup2(float x) {
    u64 d; asm("mov.b64 %0, {%1, %1};" : "=l"(d) : "f"(x)); return d;
}
__device__ __forceinline__ void unpack2(u64 v, float& lo, float& hi) {
    asm("mov.b64 {%0, %1}, %2;" : "=f"(lo), "=f"(hi) : "l"(v));
}
__device__ __forceinline__ void cp16(float* s, const float* g) {
    unsigned sa = (unsigned)__cvta_generic_to_shared(s);
    asm volatile("cp.async.cg.shared.global [%0], [%1], 16;" :: "r"(sa), "l"(g));
}
__device__ __forceinline__ void cp_commit() { asm volatile("cp.async.commit_group;"); }
template<int W> __device__ __forceinline__ void cp_wait() {
    asm volatile("cp.async.wait_group %0;" :: "n"(W));
}
// vector reduction to gmem (no return): 4x less LSU issue than scalar atomics
__device__ __forceinline__ void red4(float* p, float a, float b, float c, float d) {
    asm volatile("red.global.add.v4.f32 [%0], {%1,%2,%3,%4};"
                 :: "l"(p), "f"(a), "f"(b), "f"(c), "f"(d) : "memory");
}

// mish(x) = x*tanh(softplus(x)) = x*(u^2+2u)/(u^2+2u+2), u = e^x
__device__ __forceinline__ float mish(float v) {
    if (v > 15.f) return v;
    float u = __expf(v);
    float w = u * (u + 2.f);
    return __fdividef(v * w, w + 2.f);
}

// ---------------- prologue kernels ------------------------------------------
__global__ void zero_agg_kernel() {
    size_t i = (size_t)blockIdx.x * blockDim.x + threadIdx.x;   // exact cover
    ((float4*)g_agg)[i] = make_float4(0.f, 0.f, 0.f, 0.f);
    if (i == 0) g_flag = 0u;
}

__global__ void detect_kernel(const unsigned* __restrict__ w) {
    unsigned loc = 0;
    for (int i = blockIdx.x * blockDim.x + threadIdx.x; i < NE;
         i += gridDim.x * blockDim.x)
        loc |= w[2 * i + 1];
    if (__syncthreads_or(loc != 0))
        if (threadIdx.x == 0) atomicOr(&g_flag, 1u);
}

__global__ void convert_kernel(const void* __restrict__ ei) {
    int i = blockIdx.x * blockDim.x + threadIdx.x;
    if (i >= NE) return;
    if (g_flag == 0u) {                              // int64 payload
        const long long* p = (const long long*)ei;
        g_src[i] = (int)p[i];
        g_dst[i] = (int)p[NE + i];
    } else {                                         // int32 payload
        const int* p = (const int*)ei;
        g_src[i] = p[i];
        g_dst[i] = p[NE + i];
    }
}

// ---------------- fused edge-message kernel ---------------------------------
// 64 edges/CTA, 256 threads, thread tile 8x8 (f32x2 accs).
// smem (floats): [0,4096)       A dbuf (2 x 32k x 64) / GEMM2 W2 buf1
//                [4096,20480)   B dbuf (2 x 32k x 256) / H[64][256]
//                [20480,24576)  W2 buf0 (16k x 256)
// Total 96 KB -> 2 CTAs/SM.
#define EB_OFF 4096
#define EW_OFF 20480
#define EDGE_SMEM (24576 * 4)

__global__ void __launch_bounds__(256, 2)
edge_kernel(const float* __restrict__ x, const float* __restrict__ ea,
            const float* __restrict__ W1, const float* __restrict__ b1,
            const float* __restrict__ W2, const float* __restrict__ b2)
{
    extern __shared__ float sm[];
    __shared__ int sdst[64];

    const int tid = threadIdx.x;
    const int cx = tid & 31;      // cols [8cx, 8cx+8)
    const int cy = tid >> 5;      // rows [8cy, 8cy+8)
    const int e = tid & 63;       // gather: edge within CTA
    const int part = tid >> 6;    // gather: 4 threads per edge, 8 k each

    const int eg = blockIdx.x * 64 + e;
    const int sidx = g_src[eg], didx = g_dst[eg];
    if (part == 0) sdst[e] = didx;
    const float* xd  = x + (size_t)didx * ND;
    const float* xs  = x + (size_t)sidx * ND;
    const float* eap = ea + (size_t)eg * ED;

    // prologue: gather chunk 0, prefetch W1 chunk 0
    {
        int kb = part * 8;
        const float* p = xd + kb;   // chunk 0 always in x[dst]
        float4 r0 = *(const float4*)p, r1 = *(const float4*)(p + 4);
        float* a = sm + (part * 8) * 64 + e;
        a[0] = r0.x; a[64] = r0.y; a[128] = r0.z; a[192] = r0.w;
        a[256] = r1.x; a[320] = r1.y; a[384] = r1.z; a[448] = r1.w;
    }
    #pragma unroll
    for (int i = 0; i < 8; ++i) { int j = tid + 256 * i; cp16(sm + EB_OFF + j * 4, W1 + j * 4); }
    cp_commit();

    u64 acc[8][4];
    {
        const u64* bp = (const u64*)b1 + cx * 4;
        #pragma unroll
        for (int j = 0; j < 4; ++j) {
            u64 bv = bp[j];
            #pragma unroll
            for (int i = 0; i < 8; ++i) acc[i][j] = bv;
        }
    }

    // GEMM1: [64 x 448] @ [448 x 256], 14 k-chunks of 32
    #pragma unroll 1
    for (int s = 0; s < 14; ++s) {
        cp_wait<0>();
        __syncthreads();
        float4 r0, r1;
        const bool more = (s + 1 < 14);
        if (more) {
            const float* g = W1 + (s + 1) * 8192;
            float* buf = sm + EB_OFF + ((s + 1) & 1) * 8192;
            #pragma unroll
            for (int i = 0; i < 8; ++i) { int j = tid + 256 * i; cp16(buf + j * 4, g + j * 4); }
            cp_commit();
            int kb = 32 * (s + 1) + part * 8;
            const float* p = (kb < 128) ? xd + kb
                           : (kb < 256) ? xs + (kb - 128)
                                        : eap + (kb - 256);
            r0 = *(const float4*)p; r1 = *(const float4*)(p + 4);
        } else {
            // prefetch W2 chunk 0 into the idle EW region
            #pragma unroll
            for (int i = 0; i < 4; ++i) { int j = tid + 256 * i; cp16(sm + EW_OFF + j * 4, W2 + j * 4); }
            cp_commit();
        }
        const float* Asb = sm + (s & 1) * 2048;
        const float* Bsb = sm + EB_OFF + (s & 1) * 8192;
        #pragma unroll 4
        for (int kk = 0; kk < 32; ++kk) {
            const float* arow = Asb + kk * 64 + cy * 8;   // warp-uniform bcast
            float4 aA = *(const float4*)arow;
            float4 aB = *(const float4*)(arow + 4);
            const ulonglong2* brow = (const ulonglong2*)(Bsb + kk * 256 + cx * 8);
            ulonglong2 B0 = brow[0], B1 = brow[1];
            float av[8] = {aA.x, aA.y, aA.z, aA.w, aB.x, aB.y, aB.z, aB.w};
            #pragma unroll
            for (int i = 0; i < 8; ++i) {
                u64 ad = dup2(av[i]);
                acc[i][0] = ffma2(B0.x, ad, acc[i][0]);
                acc[i][1] = ffma2(B0.y, ad, acc[i][1]);
                acc[i][2] = ffma2(B1.x, ad, acc[i][2]);
                acc[i][3] = ffma2(B1.y, ad, acc[i][3]);
            }
        }
        if (more) {
            float* a = sm + ((s + 1) & 1) * 2048 + (part * 8) * 64 + e;
            a[0] = r0.x; a[64] = r0.y; a[128] = r0.z; a[192] = r0.w;
            a[256] = r1.x; a[320] = r1.y; a[384] = r1.z; a[448] = r1.w;
        }
    }

    __syncthreads();   // all GEMM1 smem reads done before H overwrites B region

    // mish -> H[64][256] in the B region
    float* Hs = sm + EB_OFF;
    #pragma unroll
    for (int i = 0; i < 8; ++i) {
        float v[8];
        #pragma unroll
        for (int j = 0; j < 4; ++j) unpack2(acc[i][j], v[2 * j], v[2 * j + 1]);
        #pragma unroll
        for (int j = 0; j < 8; ++j) v[j] = mish(v[j]);
        float* hp = Hs + (cy * 8 + i) * 256 + cx * 8;
        *(float4*)hp       = make_float4(v[0], v[1], v[2], v[3]);
        *(float4*)(hp + 4) = make_float4(v[4], v[5], v[6], v[7]);
    }

    {
        const u64* bp = (const u64*)b2 + cx * 4;
        #pragma unroll
        for (int j = 0; j < 4; ++j) {
            u64 bv = bp[j];
            #pragma unroll
            for (int i = 0; i < 8; ++i) acc[i][j] = bv;
        }
    }

    // GEMM2: [64 x 256] @ [256 x 256], 16 k-chunks of 16, W2 dbuf EW/A regions
    #pragma unroll 1
    for (int s = 0; s < 16; ++s) {
        cp_wait<0>();
        __syncthreads();
        if (s + 1 < 16) {
            const float* g = W2 + (s + 1) * 4096;
            float* buf = ((s + 1) & 1) ? sm : sm + EW_OFF;
            #pragma unroll
            for (int i = 0; i < 4; ++i) { int j = tid + 256 * i; cp16(buf + j * 4, g + j * 4); }
            cp_commit();
        }
        const float* Bsb = (s & 1) ? sm : sm + EW_OFF;
        const float* hbase = Hs + (cy * 8) * 256;
        #pragma unroll 4
        for (int kk = 0; kk < 16; ++kk) {
            int k = s * 16 + kk;
            const ulonglong2* brow = (const ulonglong2*)(Bsb + kk * 256 + cx * 8);
            ulonglong2 B0 = brow[0], B1 = brow[1];
            #pragma unroll
            for (int i = 0; i < 8; ++i) {
                u64 ad = dup2(hbase[i * 256 + k]);   // warp-uniform bcast
                acc[i][0] = ffma2(B0.x, ad, acc[i][0]);
                acc[i][1] = ffma2(B0.y, ad, acc[i][1]);
                acc[i][2] = ffma2(B1.x, ad, acc[i][2]);
                acc[i][3] = ffma2(B1.y, ad, acc[i][3]);
            }
        }
    }

    // scatter-add msg into g_agg[dst] via vector REDG
    #pragma unroll
    for (int i = 0; i < 8; ++i) {
        float v[8];
        #pragma unroll
        for (int j = 0; j < 4; ++j) unpack2(acc[i][j], v[2 * j], v[2 * j + 1]);
        float* p = g_agg + (size_t)sdst[cy * 8 + i] * HD + cx * 8;
        red4(p,     v[0], v[1], v[2], v[3]);
        red4(p + 4, v[4], v[5], v[6], v[7]);
    }
}

// ---------------- fused node-update kernel ----------------------------------
// 64 nodes/CTA, 256 threads. GEMM1 tile 8x8 (out 256); GEMM2 tile 4x8
// (out 128); residual + register LayerNorm (shfl over 16-lane groups).
// smem (floats): [0,4096) A dbuf / U2 buf1; [4096,20480) U1 dbuf / H;
//                [20480,24576) U2 buf0. Total 96 KB -> 2 CTAs/SM.
#define NODE_SMEM (24576 * 4)

__global__ void __launch_bounds__(256, 2)
node_kernel(const float* __restrict__ x,
            const float* __restrict__ U1, const float* __restrict__ c1,
            const float* __restrict__ U2, const float* __restrict__ c2,
            const float* __restrict__ gamma, const float* __restrict__ beta,
            float* __restrict__ out)
{
    extern __shared__ float sm[];
    const int tid = threadIdx.x;
    const int cx = tid & 31, cy = tid >> 5;
    const int e = tid & 63, part = tid >> 6;
    const int nbase = blockIdx.x * 64;

    int gnode = nbase + e;
    if (gnode >= NN) gnode = 0;
    const float* xp = x + (size_t)gnode * ND;
    const float* ap = g_agg + (size_t)gnode * HD;

    // prologue: gather chunk 0, prefetch U1 chunk 0
    {
        int kb = part * 8;
        const float* p = xp + kb;   // chunk 0 in x
        float4 r0 = *(const float4*)p, r1 = *(const float4*)(p + 4);
        float* a = sm + (part * 8) * 64 + e;
        a[0] = r0.x; a[64] = r0.y; a[128] = r0.z; a[192] = r0.w;
        a[256] = r1.x; a[320] = r1.y; a[384] = r1.z; a[448] = r1.w;
    }
    #pragma unroll
    for (int i = 0; i < 8; ++i) { int j = tid + 256 * i; cp16(sm + EB_OFF + j * 4, U1 + j * 4); }
    cp_commit();

    u64 acc[8][4];
    {
        const u64* bp = (const u64*)c1 + cx * 4;
        #pragma unroll
        for (int j = 0; j < 4; ++j) {
            u64 bv = bp[j];
            #pragma unroll
            for (int i = 0; i < 8; ++i) acc[i][j] = bv;
        }
    }

    // GEMM1: [64 x 384] @ [384 x 256], 12 k-chunks of 32
    #pragma unroll 1
    for (int s = 0; s < 12; ++s) {
        cp_wait<0>();
        __syncthreads();
        float4 r0, r1;
        const bool more = (s + 1 < 12);
        if (more) {
            const float* g = U1 + (s + 1) * 8192;
            float* buf = sm + EB_OFF + ((s + 1) & 1) * 8192;
            #pragma unroll
            for (int i = 0; i < 8; ++i) { int j = tid + 256 * i; cp16(buf + j * 4, g + j * 4); }
            cp_commit();
            int kb = 32 * (s + 1) + part * 8;
            const float* p = (kb < 128) ? xp + kb : ap + (kb - 128);
            r0 = *(const float4*)p; r1 = *(const float4*)(p + 4);
        } else {
            // prefetch U2 chunk 0
            #pragma unroll
            for (int i = 0; i < 4; ++i) { int j = tid + 256 * i; cp16(sm + EW_OFF + j * 4, U2 + j * 4); }
            cp_commit();
        }
        const float* Asb = sm + (s & 1) * 2048;
        const float* Bsb = sm + EB_OFF + (s & 1) * 8192;
        #pragma unroll 4
        for (int kk = 0; kk < 32; ++kk) {
            const float* arow = Asb + kk * 64 + cy * 8;
            float4 aA = *(const float4*)arow;
            float4 aB = *(const float4*)(arow + 4);
            const ulonglong2* brow = (const ulonglong2*)(Bsb + kk * 256 + cx * 8);
            ulonglong2 B0 = brow[0], B1 = brow[1];
            float av[8] = {aA.x, aA.y, aA.z, aA.w, aB.x, aB.y, aB.z, aB.w};
            #pragma unroll
            for (int i = 0; i < 8; ++i) {
                u64 ad = dup2(av[i]);
                acc[i][0] = ffma2(B0.x, ad, acc[i][0]);
                acc[i][1] = ffma2(B0.y, ad, acc[i][1]);
                acc[i][2] = ffma2(B1.x, ad, acc[i][2]);
                acc[i][3] = ffma2(B1.y, ad, acc[i][3]);
            }
        }
        if (more) {
            float* a = sm + ((s + 1) & 1) * 2048 + (part * 8) * 64 + e;
            a[0] = r0.x; a[64] = r0.y; a[128] = r0.z; a[192] = r0.w;
            a[256] = r1.x; a[320] = r1.y; a[384] = r1.z; a[448] = r1.w;
        }
    }

    __syncthreads();

    // mish -> H[64][256]
    float* Hs = sm + EB_OFF;
    #pragma unroll
    for (int i = 0; i < 8; ++i) {
        float v[8];
        #pragma unroll
        for (int j = 0; j < 4; ++j) unpack2(acc[i][j], v[2 * j], v[2 * j + 1]);
        #pragma unroll
        for (int j = 0; j < 8; ++j) v[j] = mish(v[j]);
        float* hp = Hs + (cy * 8 + i) * 256 + cx * 8;
        *(float4*)hp       = make_float4(v[0], v[1], v[2], v[3]);
        *(float4*)(hp + 4) = make_float4(v[4], v[5], v[6], v[7]);
    }

    // GEMM2: [64 x 256] @ [256 x 128], 8 k-chunks of 32, tile 4x8
    const int cx2 = tid & 15, cy2 = tid >> 4;
    u64 acc2[4][4];
    {
        const u64* bp = (const u64*)c2 + cx2 * 4;
        #pragma unroll
        for (int j = 0; j < 4; ++j) {
            u64 bv = bp[j];
            #pragma unroll
            for (int i = 0; i < 4; ++i) acc2[i][j] = bv;
        }
    }

    #pragma unroll 1
    for (int s = 0; s < 8; ++s) {
        cp_wait<0>();
        __syncthreads();
        if (s + 1 < 8) {
            const float* g = U2 + (s + 1) * 4096;
            float* buf = ((s + 1) & 1) ? sm : sm + EW_OFF;
            #pragma unroll
            for (int i = 0; i < 4; ++i) { int j = tid + 256 * i; cp16(buf + j * 4, g + j * 4); }
            cp_commit();
        }
        const float* Bsb = (s & 1) ? sm : sm + EW_OFF;
        const float* hbase = Hs + (cy2 * 4) * 256;
        #pragma unroll 4
        for (int kk = 0; kk < 32; ++kk) {
            int k = s * 32 + kk;
            const ulonglong2* brow = (const ulonglong2*)(Bsb + kk * 128 + cx2 * 8);
            ulonglong2 B0 = brow[0], B1 = brow[1];
            #pragma unroll
            for (int i = 0; i < 4; ++i) {
                u64 ad = dup2(hbase[i * 256 + k]);
                acc2[i][0] = ffma2(B0.x, ad, acc2[i][0]);
                acc2[i][1] = ffma2(B0.y, ad, acc2[i][1]);
                acc2[i][2] = ffma2(B1.x, ad, acc2[i][2]);
                acc2[i][3] = ffma2(B1.y, ad, acc2[i][3]);
            }
        }
    }

    // residual + LayerNorm entirely in registers (16-lane shfl groups per row)
    float g8[8], be8[8];
    {
        float4 t0 = *(const float4*)(gamma + cx2 * 8);
        float4 t1 = *(const float4*)(gamma + cx2 * 8 + 4);
        g8[0]=t0.x; g8[1]=t0.y; g8[2]=t0.z; g8[3]=t0.w;
        g8[4]=t1.x; g8[5]=t1.y; g8[6]=t1.z; g8[7]=t1.w;
        float4 u0 = *(const float4*)(beta + cx2 * 8);
        float4 u1 = *(const float4*)(beta + cx2 * 8 + 4);
        be8[0]=u0.x; be8[1]=u0.y; be8[2]=u0.z; be8[3]=u0.w;
        be8[4]=u1.x; be8[5]=u1.y; be8[6]=u1.z; be8[7]=u1.w;
    }
    #pragma unroll
    for (int i = 0; i < 4; ++i) {
        const int row = cy2 * 4 + i;
        const int node = nbase + row;
        float v[8];
        #pragma unroll
        for (int j = 0; j < 4; ++j) unpack2(acc2[i][j], v[2 * j], v[2 * j + 1]);
        if (node < NN) {
            const float* xr = x + (size_t)node * ND + cx2 * 8;
            float4 r0 = *(const float4*)xr, r1 = *(const float4*)(xr + 4);
            v[0]+=r0.x; v[1]+=r0.y; v[2]+=r0.z; v[3]+=r0.w;
            v[4]+=r1.x; v[5]+=r1.y; v[6]+=r1.z; v[7]+=r1.w;
        }
        float s1 = 0.f, s2 = 0.f;
        #pragma unroll
        for (int j = 0; j < 8; ++j) { s1 += v[j]; s2 += v[j] * v[j]; }
        #pragma unroll
        for (int off = 1; off < 16; off <<= 1) {
            s1 += __shfl_xor_sync(0xFFFFFFFFu, s1, off);
            s2 += __shfl_xor_sync(0xFFFFFFFFu, s2, off);
        }
        float mu = s1 * (1.f / 128.f);
        float var = s2 * (1.f / 128.f) - mu * mu;
        float r = rsqrtf(var + 1e-5f);
        if (node < NN) {
            float* op = out + (size_t)node * ND + cx2 * 8;
            float4 o0, o1;
            o0.x = (v[0]-mu)*r*g8[0]+be8[0]; o0.y = (v[1]-mu)*r*g8[1]+be8[1];
            o0.z = (v[2]-mu)*r*g8[2]+be8[2]; o0.w = (v[3]-mu)*r*g8[3]+be8[3];
            o1.x = (v[4]-mu)*r*g8[4]+be8[4]; o1.y = (v[5]-mu)*r*g8[5]+be8[5];
            o1.z = (v[6]-mu)*r*g8[6]+be8[6]; o1.w = (v[7]-mu)*r*g8[7]+be8[7];
            *(float4*)op       = o0;
            *(float4*)(op + 4) = o1;
        }
    }
}

// ---------------- launch ------------------------------------------------
extern "C" void kernel_launch(void* const* d_in, const int* in_sizes, int n_in,
                              void* d_out, int out_size) {
    (void)in_sizes; (void)n_in; (void)out_size;
    const float* x     = (const float*)d_in[0];
    const void*  ei    = d_in[1];
    const float* ea    = (const float*)d_in[2];
    const float* W1    = (const float*)d_in[3];
    const float* b1    = (const float*)d_in[4];
    const float* W2    = (const float*)d_in[5];
    const float* b2    = (const float*)d_in[6];
    const float* U1    = (const float*)d_in[7];
    const float* c1    = (const float*)d_in[8];
    const float* U2    = (const float*)d_in[9];
    const float* c2    = (const float*)d_in[10];
    const float* gamma = (const float*)d_in[11];
    const float* beta  = (const float*)d_in[12];
    float* out = (float*)d_out;

    static bool attr_set = false;
    if (!attr_set) {
        cudaFuncSetAttribute(edge_kernel, cudaFuncAttributeMaxDynamicSharedMemorySize, EDGE_SMEM);
        cudaFuncSetAttribute(node_kernel, cudaFuncAttributeMaxDynamicSharedMemorySize, NODE_SMEM);
        attr_set = true;
    }

    zero_agg_kernel<<<12500, 256>>>();
    detect_kernel<<<128, 256>>>((const unsigned*)ei);
    convert_kernel<<<(NE + 255) / 256, 256>>>(ei);
    edge_kernel<<<NE / 64, 256, EDGE_SMEM>>>(x, ea, W1, b1, W2, b2);
    node_kernel<<<(NN + 63) / 64, 256, NODE_SMEM>>>(x, U1, c1, U2, c2, gamma, beta, out);
}

// round 15
// speedup vs baseline: 1.3315x; 1.0482x over previous
#include <cuda_runtime.h>

#define NN 50000
#define NE 400000
#define ND 128
#define ED 192
#define HD 256

typedef unsigned long long u64;

// Scratch: allocations banned -> device globals.
__device__ __align__(16) float g_agg[(size_t)NN * HD];   // 51.2 MB
__device__ int g_src[NE];
__device__ int g_dst[NE];
__device__ unsigned g_flag;   // 0 => edge_index payload is int64

// ---- packed f32x2 helpers (FFMA2: 2x fp32 throughput) ----------------------
__device__ __forceinline__ u64 ffma2(u64 a, u64 b, u64 c) {
    u64 d; asm("fma.rn.f32x2 %0, %1, %2, %3;" : "=l"(d) : "l"(a), "l"(b), "l"(c)); return d;
}
__device__ __forceinline__ u64 dup2(float x) {
    u64 d; asm("mov.b64 %0, {%1, %1};" : "=l"(d) : "f"(x)); return d;
}
__device__ __forceinline__ void unpack2(u64 v, float& lo, float& hi) {
    asm("mov.b64 {%0, %1}, %2;" : "=f"(lo), "=f"(hi) : "l"(v));
}
__device__ __forceinline__ void cp16(float* s, const float* g) {
    unsigned sa = (unsigned)__cvta_generic_to_shared(s);
    asm volatile("cp.async.cg.shared.global [%0], [%1], 16;" :: "r"(sa), "l"(g));
}
__device__ __forceinline__ void cp_commit() { asm volatile("cp.async.commit_group;"); }
template<int W> __device__ __forceinline__ void cp_wait() {
    asm volatile("cp.async.wait_group %0;" :: "n"(W));
}
// vector reduction to gmem (no return)
__device__ __forceinline__ void red4(float* p, float a, float b, float c, float d) {
    asm volatile("red.global.add.v4.f32 [%0], {%1,%2,%3,%4};"
                 :: "l"(p), "f"(a), "f"(b), "f"(c), "f"(d) : "memory");
}

// mish(x) = x*tanh(softplus(x)) = x*(u^2+2u)/(u^2+2u+2), u = e^x
__device__ __forceinline__ float mish(float v) {
    if (v > 15.f) return v;
    float u = __expf(v);
    float w = u * (u + 2.f);
    return __fdividef(v * w, w + 2.f);
}

// ---------------- prologue kernels ------------------------------------------
__global__ void zero_agg_kernel() {
    size_t i = (size_t)blockIdx.x * blockDim.x + threadIdx.x;   // exact cover
    ((float4*)g_agg)[i] = make_float4(0.f, 0.f, 0.f, 0.f);
    if (i == 0) g_flag = 0u;
}

__global__ void detect_kernel(const unsigned* __restrict__ w) {
    unsigned loc = 0;
    for (int i = blockIdx.x * blockDim.x + threadIdx.x; i < NE;
         i += gridDim.x * blockDim.x)
        loc |= w[2 * i + 1];
    if (__syncthreads_or(loc != 0))
        if (threadIdx.x == 0) atomicOr(&g_flag, 1u);
}

__global__ void convert_kernel(const void* __restrict__ ei) {
    int i = blockIdx.x * blockDim.x + threadIdx.x;
    if (i >= NE) return;
    if (g_flag == 0u) {                              // int64 payload
        const long long* p = (const long long*)ei;
        g_src[i] = (int)p[i];
        g_dst[i] = (int)p[NE + i];
    } else {                                         // int32 payload
        const int* p = (const int*)ei;
        g_src[i] = p[i];
        g_dst[i] = p[NE + i];
    }
}

// ---------------- fused edge-message kernel ---------------------------------
// 64 edges/CTA, 256 threads, thread tile 8x8 (f32x2 accs).
// GEMM1 warp mapping: warp owns a 32-col stripe (cxa = warp*4 + lane&3,
// cya = lane>>2) -> B row read once per warp (broadcast), not 8x.
// GEMM2 keeps the old mapping (H read is warp-uniform broadcast there).
// smem (floats): [0,4096)       A dbuf / GEMM2 W2 buf1
//                [4096,20480)   B dbuf / H[64][256]
//                [20480,24576)  W2 buf0
// Total 96 KB -> 2 CTAs/SM.
#define EB_OFF 4096
#define EW_OFF 20480
#define EDGE_SMEM (24576 * 4)

__global__ void __launch_bounds__(256, 2)
edge_kernel(const float* __restrict__ x, const float* __restrict__ ea,
            const float* __restrict__ W1, const float* __restrict__ b1,
            const float* __restrict__ W2, const float* __restrict__ b2)
{
    extern __shared__ float sm[];
    __shared__ int sdst[64];

    const int tid = threadIdx.x;
    const int cx = tid & 31;                         // GEMM2 mapping
    const int cy = tid >> 5;
    const int cxa = ((tid >> 5) << 2) | (tid & 3);   // GEMM1 mapping (stripe)
    const int cya = (tid >> 2) & 7;
    const int e = tid & 63;       // gather: edge within CTA
    const int part = tid >> 6;    // gather: 4 threads per edge, 8 k each

    const int eg = blockIdx.x * 64 + e;
    const int sidx = g_src[eg], didx = g_dst[eg];
    if (part == 0) sdst[e] = didx;
    const float* xd  = x + (size_t)didx * ND;
    const float* xs  = x + (size_t)sidx * ND;
    const float* eap = ea + (size_t)eg * ED;

    // prologue: gather chunk 0, prefetch W1 chunk 0
    {
        int kb = part * 8;
        const float* p = xd + kb;   // chunk 0 always in x[dst]
        float4 r0 = *(const float4*)p, r1 = *(const float4*)(p + 4);
        float* a = sm + (part * 8) * 64 + e;
        a[0] = r0.x; a[64] = r0.y; a[128] = r0.z; a[192] = r0.w;
        a[256] = r1.x; a[320] = r1.y; a[384] = r1.z; a[448] = r1.w;
    }
    #pragma unroll
    for (int i = 0; i < 8; ++i) { int j = tid + 256 * i; cp16(sm + EB_OFF + j * 4, W1 + j * 4); }
    cp_commit();

    u64 acc[8][4];
    {
        const u64* bp = (const u64*)b1 + cxa * 4;
        #pragma unroll
        for (int j = 0; j < 4; ++j) {
            u64 bv = bp[j];
            #pragma unroll
            for (int i = 0; i < 8; ++i) acc[i][j] = bv;
        }
    }

    // GEMM1: [64 x 448] @ [448 x 256], 14 k-chunks of 32
    #pragma unroll 1
    for (int s = 0; s < 14; ++s) {
        cp_wait<0>();
        __syncthreads();
        float4 r0, r1;
        const bool more = (s + 1 < 14);
        if (more) {
            const float* g = W1 + (s + 1) * 8192;
            float* buf = sm + EB_OFF + ((s + 1) & 1) * 8192;
            #pragma unroll
            for (int i = 0; i < 8; ++i) { int j = tid + 256 * i; cp16(buf + j * 4, g + j * 4); }
            cp_commit();
            int kb = 32 * (s + 1) + part * 8;
            const float* p = (kb < 128) ? xd + kb
                           : (kb < 256) ? xs + (kb - 128)
                                        : eap + (kb - 256);
            r0 = *(const float4*)p; r1 = *(const float4*)(p + 4);
        } else {
            // prefetch W2 chunk 0 into the idle EW region
            #pragma unroll
            for (int i = 0; i < 4; ++i) { int j = tid + 256 * i; cp16(sm + EW_OFF + j * 4, W2 + j * 4); }
            cp_commit();
        }
        const float* Asb = sm + (s & 1) * 2048;
        const float* Bsb = sm + EB_OFF + (s & 1) * 8192;
        #pragma unroll 4
        for (int kk = 0; kk < 32; ++kk) {
            const float* arow = Asb + kk * 64 + cya * 8;
            float4 aA = *(const float4*)arow;
            float4 aB = *(const float4*)(arow + 4);
            const ulonglong2* brow = (const ulonglong2*)(Bsb + kk * 256 + cxa * 8);
            ulonglong2 B0 = brow[0], B1 = brow[1];
            float av[8] = {aA.x, aA.y, aA.z, aA.w, aB.x, aB.y, aB.z, aB.w};
            #pragma unroll
            for (int i = 0; i < 8; ++i) {
                u64 ad = dup2(av[i]);
                acc[i][0] = ffma2(B0.x, ad, acc[i][0]);
                acc[i][1] = ffma2(B0.y, ad, acc[i][1]);
                acc[i][2] = ffma2(B1.x, ad, acc[i][2]);
                acc[i][3] = ffma2(B1.y, ad, acc[i][3]);
            }
        }
        if (more) {
            float* a = sm + ((s + 1) & 1) * 2048 + (part * 8) * 64 + e;
            a[0] = r0.x; a[64] = r0.y; a[128] = r0.z; a[192] = r0.w;
            a[256] = r1.x; a[320] = r1.y; a[384] = r1.z; a[448] = r1.w;
        }
    }

    __syncthreads();   // all GEMM1 smem reads done before H overwrites B region

    // mish -> H[64][256] in the B region (GEMM1 mapping)
    float* Hs = sm + EB_OFF;
    #pragma unroll
    for (int i = 0; i < 8; ++i) {
        float v[8];
        #pragma unroll
        for (int j = 0; j < 4; ++j) unpack2(acc[i][j], v[2 * j], v[2 * j + 1]);
        #pragma unroll
        for (int j = 0; j < 8; ++j) v[j] = mish(v[j]);
        float* hp = Hs + (cya * 8 + i) * 256 + cxa * 8;
        *(float4*)hp       = make_float4(v[0], v[1], v[2], v[3]);
        *(float4*)(hp + 4) = make_float4(v[4], v[5], v[6], v[7]);
    }

    {
        const u64* bp = (const u64*)b2 + cx * 4;
        #pragma unroll
        for (int j = 0; j < 4; ++j) {
            u64 bv = bp[j];
            #pragma unroll
            for (int i = 0; i < 8; ++i) acc[i][j] = bv;
        }
    }

    // GEMM2: [64 x 256] @ [256 x 256], 16 k-chunks of 16 (old mapping)
    #pragma unroll 1
    for (int s = 0; s < 16; ++s) {
        cp_wait<0>();
        __syncthreads();
        if (s + 1 < 16) {
            const float* g = W2 + (s + 1) * 4096;
            float* buf = ((s + 1) & 1) ? sm : sm + EW_OFF;
            #pragma unroll
            for (int i = 0; i < 4; ++i) { int j = tid + 256 * i; cp16(buf + j * 4, g + j * 4); }
            cp_commit();
        }
        const float* Bsb = (s & 1) ? sm : sm + EW_OFF;
        const float* hbase = Hs + (cy * 8) * 256;
        #pragma unroll 4
        for (int kk = 0; kk < 16; ++kk) {
            int k = s * 16 + kk;
            const ulonglong2* brow = (const ulonglong2*)(Bsb + kk * 256 + cx * 8);
            ulonglong2 B0 = brow[0], B1 = brow[1];
            #pragma unroll
            for (int i = 0; i < 8; ++i) {
                u64 ad = dup2(hbase[i * 256 + k]);   // warp-uniform bcast
                acc[i][0] = ffma2(B0.x, ad, acc[i][0]);
                acc[i][1] = ffma2(B0.y, ad, acc[i][1]);
                acc[i][2] = ffma2(B1.x, ad, acc[i][2]);
                acc[i][3] = ffma2(B1.y, ad, acc[i][3]);
            }
        }
    }

    // scatter-add msg into g_agg[dst] via vector REDG
    #pragma unroll
    for (int i = 0; i < 8; ++i) {
        float v[8];
        #pragma unroll
        for (int j = 0; j < 4; ++j) unpack2(acc[i][j], v[2 * j], v[2 * j + 1]);
        float* p = g_agg + (size_t)sdst[cy * 8 + i] * HD + cx * 8;
        red4(p,     v[0], v[1], v[2], v[3]);
        red4(p + 4, v[4], v[5], v[6], v[7]);
    }
}

// ---------------- fused node-update kernel ----------------------------------
// 64 nodes/CTA, 256 threads. GEMM1 tile 8x8 striped mapping (like edge);
// GEMM2 tile 4x8 + LN keep the old mapping (shfl groups need it).
#define NODE_SMEM (24576 * 4)

__global__ void __launch_bounds__(256, 2)
node_kernel(const float* __restrict__ x,
            const float* __restrict__ U1, const float* __restrict__ c1,
            const float* __restrict__ U2, const float* __restrict__ c2,
            const float* __restrict__ gamma, const float* __restrict__ beta,
            float* __restrict__ out)
{
    extern __shared__ float sm[];
    const int tid = threadIdx.x;
    const int cxa = ((tid >> 5) << 2) | (tid & 3);
    const int cya = (tid >> 2) & 7;
    const int e = tid & 63, part = tid >> 6;
    const int nbase = blockIdx.x * 64;

    int gnode = nbase + e;
    if (gnode >= NN) gnode = 0;
    const float* xp = x + (size_t)gnode * ND;
    const float* ap = g_agg + (size_t)gnode * HD;

    // prologue: gather chunk 0, prefetch U1 chunk 0
    {
        int kb = part * 8;
        const float* p = xp + kb;
        float4 r0 = *(const float4*)p, r1 = *(const float4*)(p + 4);
        float* a = sm + (part * 8) * 64 + e;
        a[0] = r0.x; a[64] = r0.y; a[128] = r0.z; a[192] = r0.w;
        a[256] = r1.x; a[320] = r1.y; a[384] = r1.z; a[448] = r1.w;
    }
    #pragma unroll
    for (int i = 0; i < 8; ++i) { int j = tid + 256 * i; cp16(sm + EB_OFF + j * 4, U1 + j * 4); }
    cp_commit();

    u64 acc[8][4];
    {
        const u64* bp = (const u64*)c1 + cxa * 4;
        #pragma unroll
        for (int j = 0; j < 4; ++j) {
            u64 bv = bp[j];
            #pragma unroll
            for (int i = 0; i < 8; ++i) acc[i][j] = bv;
        }
    }

    // GEMM1: [64 x 384] @ [384 x 256], 12 k-chunks of 32
    #pragma unroll 1
    for (int s = 0; s < 12; ++s) {
        cp_wait<0>();
        __syncthreads();
        float4 r0, r1;
        const bool more = (s + 1 < 12);
        if (more) {
            const float* g = U1 + (s + 1) * 8192;
            float* buf = sm + EB_OFF + ((s + 1) & 1) * 8192;
            #pragma unroll
            for (int i = 0; i < 8; ++i) { int j = tid + 256 * i; cp16(buf + j * 4, g + j * 4); }
            cp_commit();
            int kb = 32 * (s + 1) + part * 8;
            const float* p = (kb < 128) ? xp + kb : ap + (kb - 128);
            r0 = *(const float4*)p; r1 = *(const float4*)(p + 4);
        } else {
            #pragma unroll
            for (int i = 0; i < 4; ++i) { int j = tid + 256 * i; cp16(sm + EW_OFF + j * 4, U2 + j * 4); }
            cp_commit();
        }
        const float* Asb = sm + (s & 1) * 2048;
        const float* Bsb = sm + EB_OFF + (s & 1) * 8192;
        #pragma unroll 4
        for (int kk = 0; kk < 32; ++kk) {
            const float* arow = Asb + kk * 64 + cya * 8;
            float4 aA = *(const float4*)arow;
            float4 aB = *(const float4*)(arow + 4);
            const ulonglong2* brow = (const ulonglong2*)(Bsb + kk * 256 + cxa * 8);
            ulonglong2 B0 = brow[0], B1 = brow[1];
            float av[8] = {aA.x, aA.y, aA.z, aA.w, aB.x, aB.y, aB.z, aB.w};
            #pragma unroll
            for (int i = 0; i < 8; ++i) {
                u64 ad = dup2(av[i]);
                acc[i][0] = ffma2(B0.x, ad, acc[i][0]);
                acc[i][1] = ffma2(B0.y, ad, acc[i][1]);
                acc[i][2] = ffma2(B1.x, ad, acc[i][2]);
                acc[i][3] = ffma2(B1.y, ad, acc[i][3]);
            }
        }
        if (more) {
            float* a = sm + ((s + 1) & 1) * 2048 + (part * 8) * 64 + e;
            a[0] = r0.x; a[64] = r0.y; a[128] = r0.z; a[192] = r0.w;
            a[256] = r1.x; a[320] = r1.y; a[384] = r1.z; a[448] = r1.w;
        }
    }
    __syncthreads();

    // mish -> H[64][256] (GEMM1 mapping)
    float* Hs = sm + EB_OFF;
    #pragma unroll
    for (int i = 0; i < 8; ++i) {
        float v[8];
        #pragma unroll
        for (int j = 0; j < 4; ++j) unpack2(acc[i][j], v[2 * j], v[2 * j + 1]);
        #pragma unroll
        for (int j = 0; j < 8; ++j) v[j] = mish(v[j]);
        float* hp = Hs + (cya * 8 + i) * 256 + cxa * 8;
        *(float4*)hp       = make_float4(v[0], v[1], v[2], v[3]);
        *(float4*)(hp + 4) = make_float4(v[4], v[5], v[6], v[7]);
    }

    // GEMM2: [64 x 256] @ [256 x 128], 8 k-chunks of 32, tile 4x8 (old map)
    const int cx2 = tid & 15, cy2 = tid >> 4;
    u64 acc2[4][4];
    {
        const u64* bp = (const u64*)c2 + cx2 * 4;
        #pragma unroll
        for (int j = 0; j < 4; ++j) {
            u64 bv = bp[j];
            #pragma unroll
            for (int i = 0; i < 4; ++i) acc2[i][j] = bv;
        }
    }

    #pragma unroll 1
    for (int s = 0; s < 8; ++s) {
        cp_wait<0>();
        __syncthreads();
        if (s + 1 < 8) {
            const float* g = U2 + (s + 1) * 4096;
            float* buf = ((s + 1) & 1) ? sm : sm + EW_OFF;
            #pragma unroll
            for (int i = 0; i < 4; ++i) { int j = tid + 256 * i; cp16(buf + j * 4, g + j * 4); }
            cp_commit();
        }
        const float* Bsb = (s & 1) ? sm : sm + EW_OFF;
        const float* hbase = Hs + (cy2 * 4) * 256;
        #pragma unroll 4
        for (int kk = 0; kk < 32; ++kk) {
            int k = s * 32 + kk;
            const ulonglong2* brow = (const ulonglong2*)(Bsb + kk * 128 + cx2 * 8);
            ulonglong2 B0 = brow[0], B1 = brow[1];
            #pragma unroll
            for (int i = 0; i < 4; ++i) {
                u64 ad = dup2(hbase[i * 256 + k]);
                acc2[i][0] = ffma2(B0.x, ad, acc2[i][0]);
                acc2[i][1] = ffma2(B0.y, ad, acc2[i][1]);
                acc2[i][2] = ffma2(B1.x, ad, acc2[i][2]);
                acc2[i][3] = ffma2(B1.y, ad, acc2[i][3]);
            }
        }
    }

    // residual + LayerNorm in registers (16-lane shfl groups per row)
    float g8[8], be8[8];
    {
        float4 t0 = *(const float4*)(gamma + cx2 * 8);
        float4 t1 = *(const float4*)(gamma + cx2 * 8 + 4);
        g8[0]=t0.x; g8[1]=t0.y; g8[2]=t0.z; g8[3]=t0.w;
        g8[4]=t1.x; g8[5]=t1.y; g8[6]=t1.z; g8[7]=t1.w;
        float4 u0 = *(const float4*)(beta + cx2 * 8);
        float4 u1 = *(const float4*)(beta + cx2 * 8 + 4);
        be8[0]=u0.x; be8[1]=u0.y; be8[2]=u0.z; be8[3]=u0.w;
        be8[4]=u1.x; be8[5]=u1.y; be8[6]=u1.z; be8[7]=u1.w;
    }
    #pragma unroll
    for (int i = 0; i < 4; ++i) {
        const int row = cy2 * 4 + i;
        const int node = nbase + row;
        float v[8];
        #pragma unroll
        for (int j = 0; j < 4; ++j) unpack2(acc2[i][j], v[2 * j], v[2 * j + 1]);
        if (node < NN) {
            const float* xr = x + (size_t)node * ND + cx2 * 8;
            float4 r0 = *(const float4*)xr, r1 = *(const float4*)(xr + 4);
            v[0]+=r0.x; v[1]+=r0.y; v[2]+=r0.z; v[3]+=r0.w;
            v[4]+=r1.x; v[5]+=r1.y; v[6]+=r1.z; v[7]+=r1.w;
        }
        float s1 = 0.f, s2 = 0.f;
        #pragma unroll
        for (int j = 0; j < 8; ++j) { s1 += v[j]; s2 += v[j] * v[j]; }
        #pragma unroll
        for (int off = 1; off < 16; off <<= 1) {
            s1 += __shfl_xor_sync(0xFFFFFFFFu, s1, off);
            s2 += __shfl_xor_sync(0xFFFFFFFFu, s2, off);
        }
        float mu = s1 * (1.f / 128.f);
        float var = s2 * (1.f / 128.f) - mu * mu;
        float r = rsqrtf(var + 1e-5f);
        if (node < NN) {
            float* op = out + (size_t)node * ND + cx2 * 8;
            float4 o0, o1;
            o0.x = (v[0]-mu)*r*g8[0]+be8[0]; o0.y = (v[1]-mu)*r*g8[1]+be8[1];
            o0.z = (v[2]-mu)*r*g8[2]+be8[2]; o0.w = (v[3]-mu)*r*g8[3]+be8[3];
            o1.x = (v[4]-mu)*r*g8[4]+be8[4]; o1.y = (v[5]-mu)*r*g8[5]+be8[5];
            o1.z = (v[6]-mu)*r*g8[6]+be8[6]; o1.w = (v[7]-mu)*r*g8[7]+be8[7];
            *(float4*)op       = o0;
            *(float4*)(op + 4) = o1;
        }
    }
}

// ---------------- launch ------------------------------------------------
extern "C" void kernel_launch(void* const* d_in, const int* in_sizes, int n_in,
                              void* d_out, int out_size) {
    (void)in_sizes; (void)n_in; (void)out_size;
    const float* x     = (const float*)d_in[0];
    const void*  ei    = d_in[1];
    const float* ea    = (const float*)d_in[2];
    const float* W1    = (const float*)d_in[3];
    const float* b1    = (const float*)d_in[4];
    const float* W2    = (const float*)d_in[5];
    const float* b2    = (const float*)d_in[6];
    const float* U1    = (const float*)d_in[7];
    const float* c1    = (const float*)d_in[8];
    const float* U2    = (const float*)d_in[9];
    const float* c2    = (const float*)d_in[10];
    const float* gamma = (const float*)d_in[11];
    const float* beta  = (const float*)d_in[12];
    float* out = (float*)d_out;

    static bool attr_set = false;
    if (!attr_set) {
        cudaFuncSetAttribute(edge_kernel, cudaFuncAttributeMaxDynamicSharedMemorySize, EDGE_SMEM);
        cudaFuncSetAttribute(node_kernel, cudaFuncAttributeMaxDynamicSharedMemorySize, NODE_SMEM);
        attr_set = true;
    }

    zero_agg_kernel<<<12500, 256>>>();
    detect_kernel<<<128, 256>>>((const unsigned*)ei);
    convert_kernel<<<(NE + 255) / 256, 256>>>(ei);
    edge_kernel<<<NE / 64, 256, EDGE_SMEM>>>(x, ea, W1, b1, W2, b2);
    node_kernel<<<(NN + 63) / 64, 256, NODE_SMEM>>>(x, U1, c1, U2, c2, gamma, beta, out);
}